// round 15
// baseline (speedup 1.0000x reference)
#include <cuda_runtime.h>
#include <math.h>
#include <stdint.h>

#define BB 2
#define SS 2048
#define HH 1024
#define NHH 16
#define HDD 64
#define MM (BB*SS)          // 4096
#define Y_SIZE (BB*SS*HH)   // 4194304

// ---- scratch (no allocation allowed; device globals) ----
__device__ float g_Q[MM*HH];
__device__ float g_K[MM*HH];
__device__ float g_V[MM*HH];
__device__ float g_AO[MM*HH];
__device__ float g_X[MM*HH];
__device__ unsigned int g_MB[BB*SS*SS/32];  // mask bits

__device__ __forceinline__ uint32_t f2tf32(float v) {
    uint32_t r;
    asm("cvt.rna.tf32.f32 %0, %1;" : "=r"(r) : "f"(v));
    return r;
}

#define MMA_TF32(acc, a0,a1,a2,a3, b0,b1) \
    asm volatile("mma.sync.aligned.m16n8k8.row.col.f32.tf32.tf32.f32 " \
        "{%0,%1,%2,%3}, {%4,%5,%6,%7}, {%8,%9}, {%0,%1,%2,%3};" \
        : "+f"((acc)[0]), "+f"((acc)[1]), "+f"((acc)[2]), "+f"((acc)[3]) \
        : "r"(a0), "r"(a1), "r"(a2), "r"(a3), "r"(b0), "r"(b1))

__device__ __forceinline__ void ldsm_x4(uint32_t* r, uint32_t addr) {
    asm volatile("ldmatrix.sync.aligned.m8n8.x4.shared.b16 {%0,%1,%2,%3}, [%4];"
        : "=r"(r[0]), "=r"(r[1]), "=r"(r[2]), "=r"(r[3]) : "r"(addr));
}
__device__ __forceinline__ void ldsm_x2(uint32_t* r, uint32_t addr) {
    asm volatile("ldmatrix.sync.aligned.m8n8.x2.shared.b16 {%0,%1}, [%2];"
        : "=r"(r[0]), "=r"(r[1]) : "r"(addr));
}
#define LDSM_SELS() \
    const int rsel = (lane & 7) + ((lane >> 3) & 1) * 8; \
    const int cA = (lane >> 4) * 4; \
    const int rB = lane & 7; \
    const int cB = ((lane >> 3) & 1) * 4;

// ============================================================
// GEMM body (tf32 warp-MMA, 128x128 tile, RNA rounding at smem store).
// ============================================================
#define GEMM_BODY(A_, W_, EPILOGUE)                                            \
    __shared__ float As[2][128 * 20];                                          \
    __shared__ float Ws[2][128 * 20];                                          \
    const int tid = threadIdx.x;                                               \
    const int wid = tid >> 5, lane = tid & 31;                                 \
    const int wm = wid >> 2, wn = wid & 3;                                     \
    const int bm = blockIdx.y * 128, bn = blockIdx.x * 128;                    \
    LDSM_SELS();                                                               \
    const uint32_t AsU = (uint32_t)__cvta_generic_to_shared(&As[0][0]);        \
    const uint32_t WsU = (uint32_t)__cvta_generic_to_shared(&Ws[0][0]);        \
    int rowA[4], rowB[4];                                                      \
    for (int im = 0; im < 4; im++) rowA[im] = (wm*64 + im*16 + rsel)*20 + cA;  \
    for (int jn = 0; jn < 4; jn++) rowB[jn] = (wn*32 + jn*8 + rB)*20 + cB;     \
    const int p0 = tid, p1 = tid + 256;                                        \
    const int r0 = p0 >> 2, q0 = (p0 & 3) * 4;                                 \
    const int r1 = p1 >> 2, q1 = (p1 & 3) * 4;                                 \
    const float* Arow0 = A_ + (size_t)(bm + r0) * 1024 + q0;                   \
    const float* Arow1 = A_ + (size_t)(bm + r1) * 1024 + q1;                   \
    const float* Wrow0 = W_ + (size_t)(bn + r0) * 1024 + q0;                   \
    const float* Wrow1 = W_ + (size_t)(bn + r1) * 1024 + q1;                   \
    const int s0 = r0 * 20 + q0, s1 = r1 * 20 + q1;                            \
    float acc[4][4][4];                                                        \
    for (int i = 0; i < 4; i++)                                                \
        for (int j = 0; j < 4; j++)                                            \
            for (int q = 0; q < 4; q++) acc[i][j][q] = 0.f;                    \
    {                                                                          \
        float4 va0 = *(const float4*)(Arow0);                                  \
        float4 va1 = *(const float4*)(Arow1);                                  \
        float4 vw0 = *(const float4*)(Wrow0);                                  \
        float4 vw1 = *(const float4*)(Wrow1);                                  \
        uint32_t* a0 = (uint32_t*)&As[0][s0];                                  \
        a0[0]=f2tf32(va0.x); a0[1]=f2tf32(va0.y); a0[2]=f2tf32(va0.z); a0[3]=f2tf32(va0.w); \
        uint32_t* a1 = (uint32_t*)&As[0][s1];                                  \
        a1[0]=f2tf32(va1.x); a1[1]=f2tf32(va1.y); a1[2]=f2tf32(va1.z); a1[3]=f2tf32(va1.w); \
        uint32_t* w0 = (uint32_t*)&Ws[0][s0];                                  \
        w0[0]=f2tf32(vw0.x); w0[1]=f2tf32(vw0.y); w0[2]=f2tf32(vw0.z); w0[3]=f2tf32(vw0.w); \
        uint32_t* w1 = (uint32_t*)&Ws[0][s1];                                  \
        w1[0]=f2tf32(vw1.x); w1[1]=f2tf32(vw1.y); w1[2]=f2tf32(vw1.z); w1[3]=f2tf32(vw1.w); \
    }                                                                          \
    __syncthreads();                                                           \
    for (int c = 0; c < 64; c++) {                                             \
        const int buf = c & 1;                                                 \
        const uint32_t aBuf = AsU + (uint32_t)buf * (128 * 20 * 4);            \
        const uint32_t wBuf = WsU + (uint32_t)buf * (128 * 20 * 4);            \
        float4 ra0, ra1, rw0, rw1;                                             \
        if (c < 63) {                                                          \
            const int k0 = (c + 1) * 16;                                       \
            ra0 = *(const float4*)(Arow0 + k0);                                \
            ra1 = *(const float4*)(Arow1 + k0);                                \
            rw0 = *(const float4*)(Wrow0 + k0);                                \
            rw1 = *(const float4*)(Wrow1 + k0);                                \
        }                                                                      \
        for (int ks = 0; ks < 2; ks++) {                                       \
            const int kk = ks * 8;                                             \
            uint32_t af[4][4], bf[4][2];                                       \
            for (int im = 0; im < 4; im++)                                     \
                ldsm_x4(af[im], aBuf + (uint32_t)(rowA[im] + kk) * 4);         \
            for (int jn = 0; jn < 4; jn++)                                     \
                ldsm_x2(bf[jn], wBuf + (uint32_t)(rowB[jn] + kk) * 4);         \
            for (int im = 0; im < 4; im++)                                     \
                for (int jn = 0; jn < 4; jn++)                                 \
                    MMA_TF32(acc[im][jn], af[im][0], af[im][1], af[im][2], af[im][3], \
                             bf[jn][0], bf[jn][1]);                            \
        }                                                                      \
        if (c < 63) {                                                          \
            const int nxt = buf ^ 1;                                           \
            uint32_t* a0 = (uint32_t*)&As[nxt][s0];                            \
            a0[0]=f2tf32(ra0.x); a0[1]=f2tf32(ra0.y); a0[2]=f2tf32(ra0.z); a0[3]=f2tf32(ra0.w); \
            uint32_t* a1 = (uint32_t*)&As[nxt][s1];                            \
            a1[0]=f2tf32(ra1.x); a1[1]=f2tf32(ra1.y); a1[2]=f2tf32(ra1.z); a1[3]=f2tf32(ra1.w); \
            uint32_t* w0 = (uint32_t*)&Ws[nxt][s0];                            \
            w0[0]=f2tf32(rw0.x); w0[1]=f2tf32(rw0.y); w0[2]=f2tf32(rw0.z); w0[3]=f2tf32(rw0.w); \
            uint32_t* w1 = (uint32_t*)&Ws[nxt][s1];                            \
            w1[0]=f2tf32(rw1.x); w1[1]=f2tf32(rw1.y); w1[2]=f2tf32(rw1.z); w1[3]=f2tf32(rw1.w); \
        }                                                                      \
        __syncthreads();                                                       \
    }                                                                          \
    const int g = lane >> 2, t = lane & 3;                                     \
    EPILOGUE

// QKV + maskbits fused launch.
__global__ void __launch_bounds__(256, 2)
qkv_gemm_kernel(const float* __restrict__ enc,
                const float* __restrict__ WQ, const float* __restrict__ WK,
                const float* __restrict__ WV, const float* __restrict__ mask,
                float* __restrict__ Qo, float* __restrict__ Ko, float* __restrict__ Vo,
                unsigned int* __restrict__ mb) {
    const int z = blockIdx.z;
    if (z == 3) {
        const int p = blockIdx.y * 8 + blockIdx.x;        // 0..255
        size_t base = (size_t)p * 32768 + threadIdx.x;
#pragma unroll 4
        for (int j = 0; j < 128; j++) {
            size_t i = base + (size_t)j * 256;
            float m = mask[i];
            unsigned int bal = __ballot_sync(0xffffffffu, m != 0.f);
            if ((threadIdx.x & 31) == 0) mb[i >> 5] = bal;
        }
        return;
    }
    const float* Wsel = (z == 0) ? WQ : (z == 1) ? WK : WV;
    float* Csel = (z == 0) ? Qo : (z == 1) ? Ko : Vo;
    GEMM_BODY(enc, Wsel,
        {
            for (int im = 0; im < 4; im++) {
                const int rowAo = bm + wm * 64 + im * 16 + g;
                const int rowBo = rowAo + 8;
                for (int jn = 0; jn < 4; jn++) {
                    const int col = bn + wn * 32 + jn * 8 + 2 * t;
                    float2 vA = make_float2(__uint_as_float(f2tf32(acc[im][jn][0])),
                                            __uint_as_float(f2tf32(acc[im][jn][1])));
                    float2 vB = make_float2(__uint_as_float(f2tf32(acc[im][jn][2])),
                                            __uint_as_float(f2tf32(acc[im][jn][3])));
                    *(float2*)(Csel + (size_t)rowAo * 1024 + col) = vA;
                    *(float2*)(Csel + (size_t)rowBo * 1024 + col) = vB;
                }
            }
        })
}

// WO: residual-add epilogue, full fp32 output.
__global__ void __launch_bounds__(256, 2)
gemm_res_kernel(const float* __restrict__ A, const float* __restrict__ W,
                float* __restrict__ C, const float* __restrict__ res) {
    GEMM_BODY(A, W,
        {
            for (int im = 0; im < 4; im++) {
                const int rowAo = bm + wm * 64 + im * 16 + g;
                const int rowBo = rowAo + 8;
                for (int jn = 0; jn < 4; jn++) {
                    const int col = bn + wn * 32 + jn * 8 + 2 * t;
                    float2 rA = *(const float2*)(res + (size_t)rowAo * 1024 + col);
                    float2 rB2 = *(const float2*)(res + (size_t)rowBo * 1024 + col);
                    *(float2*)(C + (size_t)rowAo * 1024 + col) =
                        make_float2(acc[im][jn][0] + rA.x, acc[im][jn][1] + rA.y);
                    *(float2*)(C + (size_t)rowBo * 1024 + col) =
                        make_float2(acc[im][jn][2] + rB2.x, acc[im][jn][3] + rB2.y);
                }
            }
        })
}

// ============================================================
// Fused attention.
// Phase 1: K ping-pong between Ks/Vs regions + double-buffered mask ->
//          ONE sync per k-tile (Vs idle in phase 1).
// Phase 2: unchanged structure; attn STG hoisted before AV MMA.
// smem floats: Qs[8704]@0, KA@8704(4352), KB/Vs@13056(4352), stage@17408
// (8704; sumbuf overlays), maskA(256u)@26112, maskB(256u)@26368, invS@26624.
// Total 26752 floats = 107008 B (2 CTAs/SM).
// ============================================================
__global__ void __launch_bounds__(256, 2)
fused_attn_kernel(const float* __restrict__ Qb, const float* __restrict__ Kb,
                  const float* __restrict__ Vb, const unsigned int* __restrict__ mb,
                  float* __restrict__ attn, float* __restrict__ Ob) {
    extern __shared__ float sm[];
    float* Qs = sm;
    float* KA = sm + 8704;
    float* KB = sm + 13056;                             // = Vs in phase 2
    float* Ks = sm + 8704;                              // phase-2 alias
    float* Vs = sm + 13056;                             // phase-2 alias
    float* stage = sm + 17408;
    float* sumbuf = sm + 17408;                         // overlays stage (phase 1)
    unsigned int* maskA = (unsigned int*)(sm + 26112);
    unsigned int* maskB = (unsigned int*)(sm + 26368);
    float* invS = sm + 26624;

    const int tid = threadIdx.x;
    const int wid = tid >> 5, lane = tid & 31;
    const int wm = wid >> 2, wn = wid & 3;
    const int bh = blockIdx.y, b = bh >> 4, h = bh & 15;
    const int q0 = blockIdx.x * 128;
    LDSM_SELS();
    const int g = lane >> 2, t = lane & 3;

    const uint32_t QsU = (uint32_t)__cvta_generic_to_shared(Qs);
    const uint32_t KAU = (uint32_t)__cvta_generic_to_shared(KA);
    const uint32_t KBU = (uint32_t)__cvta_generic_to_shared(KB);
    const uint32_t KsU = KAU;
    const uint32_t StU = (uint32_t)__cvta_generic_to_shared(stage);

    int rowQ[4], rowK[2];
#pragma unroll
    for (int im = 0; im < 4; im++) rowQ[im] = (wm * 64 + im * 16 + rsel) * 68 + cA;
#pragma unroll
    for (int jn = 0; jn < 2; jn++) rowK[jn] = (wn * 16 + jn * 8 + rB) * 68 + cB;

    const float* Qbase = Qb + ((size_t)(b * SS + q0)) * HH + h * HDD;
    const float* Kbase = Kb + ((size_t)b * SS) * HH + h * HDD;
    const float* Vbase = Vb + ((size_t)b * SS) * HH + h * HDD;
    const int lr = tid >> 4, lc4 = (tid & 15) * 4;
    const int mr = tid >> 1, mw = tid & 1;

    // Q loaded once for both phases
#pragma unroll
    for (int j = 0; j < 8; j++) {
        int idx = tid + j * 256;
        int r = idx >> 4, c4 = (idx & 15) * 4;
        *(float4*)&Qs[r * 68 + c4] = *(const float4*)(Qbase + (size_t)r * HH + c4);
    }
    // phase-1 tile 0 -> KA + maskA
#pragma unroll
    for (int j = 0; j < 4; j++) {
        int r = lr + j * 16;
        *(float4*)&KA[r * 68 + lc4] = *(const float4*)(Kbase + (size_t)r * HH + lc4);
    }
    maskA[tid] = mb[(size_t)(b * SS + q0 + mr) * 64 + mw];
    __syncthreads();

    // ================= PHASE 1: row sums (K ping-pong, 1 sync/tile) =========
    float rsA[4], rsB[4];
#pragma unroll
    for (int im = 0; im < 4; im++) { rsA[im] = 0.f; rsB[im] = 0.f; }

    for (int kt = 0; kt < 32; kt++) {
        const bool pf = (kt < 31);
        const uint32_t curU = (kt & 1) ? KBU : KAU;
        float* othK = (kt & 1) ? KA : KB;
        unsigned int* curM = (kt & 1) ? maskB : maskA;
        unsigned int* othM = (kt & 1) ? maskA : maskB;

        float4 rk[4];
        unsigned int rm = 0;
        if (pf) {
            const int n1 = (kt + 1) * 64;
#pragma unroll
            for (int j = 0; j < 4; j++)
                rk[j] = *(const float4*)(Kbase + (size_t)(n1 + lr + j * 16) * HH + lc4);
            rm = mb[(size_t)(b * SS + q0 + mr) * 64 + (n1 >> 5) + mw];
        }

        float acc[4][2][4];
#pragma unroll
        for (int i = 0; i < 4; i++)
#pragma unroll
            for (int j = 0; j < 2; j++)
#pragma unroll
                for (int q = 0; q < 4; q++) acc[i][j][q] = 0.f;
#pragma unroll
        for (int ks = 0; ks < 8; ks++) {
            const int kk = ks * 8;
            uint32_t af[4][4], bf[2][2];
#pragma unroll
            for (int im = 0; im < 4; im++)
                ldsm_x4(af[im], QsU + (uint32_t)(rowQ[im] + kk) * 4);
#pragma unroll
            for (int jn = 0; jn < 2; jn++)
                ldsm_x2(bf[jn], curU + (uint32_t)(rowK[jn] + kk) * 4);
#pragma unroll
            for (int im = 0; im < 4; im++)
#pragma unroll
                for (int jn = 0; jn < 2; jn++)
                    MMA_TF32(acc[im][jn], af[im][0], af[im][1], af[im][2], af[im][3],
                             bf[jn][0], bf[jn][1]);
        }

#pragma unroll
        for (int im = 0; im < 4; im++) {
            const int rAl = wm * 64 + im * 16 + g;
            const int rBl = rAl + 8;
#pragma unroll
            for (int jn = 0; jn < 2; jn++) {
                const int bp = wn * 16 + jn * 8 + 2 * t;
                const unsigned int wA = curM[rAl * 2 + (bp >> 5)];
                const unsigned int wB = curM[rBl * 2 + (bp >> 5)];
                const int bi = bp & 31;
                if ((wA >> bi) & 1u)       rsA[im] += __expf(acc[im][jn][0] * 0.125f);
                if ((wA >> (bi + 1)) & 1u) rsA[im] += __expf(acc[im][jn][1] * 0.125f);
                if ((wB >> bi) & 1u)       rsB[im] += __expf(acc[im][jn][2] * 0.125f);
                if ((wB >> (bi + 1)) & 1u) rsB[im] += __expf(acc[im][jn][3] * 0.125f);
            }
        }
        if (pf) {
#pragma unroll
            for (int j = 0; j < 4; j++)
                *(float4*)&othK[(lr + j * 16) * 68 + lc4] = rk[j];
            othM[tid] = rm;
        }
        __syncthreads();
    }

#pragma unroll
    for (int im = 0; im < 4; im++) {
        float a = rsA[im], bb = rsB[im];
        a += __shfl_xor_sync(0xffffffffu, a, 1);
        a += __shfl_xor_sync(0xffffffffu, a, 2);
        bb += __shfl_xor_sync(0xffffffffu, bb, 1);
        bb += __shfl_xor_sync(0xffffffffu, bb, 2);
        if (t == 0) {
            sumbuf[(wm * 64 + im * 16 + g) * 4 + wn] = a;
            sumbuf[(wm * 64 + im * 16 + g + 8) * 4 + wn] = bb;
        }
    }
    __syncthreads();
    if (tid < 128) {
        float s = sumbuf[tid * 4] + sumbuf[tid * 4 + 1] +
                  sumbuf[tid * 4 + 2] + sumbuf[tid * 4 + 3];
        invS[tid] = (s > 0.f) ? 1.f / s : 0.f;
    }
    // phase-2 tile 0: K, V (row-major), maskA
    __syncthreads();
#pragma unroll
    for (int j = 0; j < 4; j++) {
        int r = lr + j * 16;
        *(float4*)&Ks[r * 68 + lc4] = *(const float4*)(Kbase + (size_t)r * HH + lc4);
        *(float4*)&Vs[r * 68 + lc4] = *(const float4*)(Vbase + (size_t)r * HH + lc4);
    }
    maskA[tid] = mb[(size_t)(b * SS + q0 + mr) * 64 + mw];
    __syncthreads();

    // ================= PHASE 2: attn write + AV =================
    float accO[4][2][4];
#pragma unroll
    for (int i = 0; i < 4; i++)
#pragma unroll
        for (int j = 0; j < 2; j++)
#pragma unroll
            for (int q = 0; q < 4; q++) accO[i][j][q] = 0.f;

    for (int kt = 0; kt < 32; kt++) {
        const int k0 = kt * 64;
        const bool pf = (kt < 31);
        float4 rk[4];
        unsigned int rm = 0;
        if (pf) {
#pragma unroll
            for (int j = 0; j < 4; j++)
                rk[j] = *(const float4*)(Kbase + (size_t)(k0 + 64 + lr + j * 16) * HH + lc4);
            rm = mb[(size_t)(b * SS + q0 + mr) * 64 + ((k0 + 64) >> 5) + mw];
        }

        // --- S = Q K^T ---
        float acc[4][2][4];
#pragma unroll
        for (int i = 0; i < 4; i++)
#pragma unroll
            for (int j = 0; j < 2; j++)
#pragma unroll
                for (int q = 0; q < 4; q++) acc[i][j][q] = 0.f;
#pragma unroll
        for (int ks = 0; ks < 8; ks++) {
            const int kk = ks * 8;
            uint32_t af[4][4], bf[2][2];
#pragma unroll
            for (int im = 0; im < 4; im++)
                ldsm_x4(af[im], QsU + (uint32_t)(rowQ[im] + kk) * 4);
#pragma unroll
            for (int jn = 0; jn < 2; jn++)
                ldsm_x2(bf[jn], KsU + (uint32_t)(rowK[jn] + kk) * 4);
#pragma unroll
            for (int im = 0; im < 4; im++)
#pragma unroll
                for (int jn = 0; jn < 2; jn++)
                    MMA_TF32(acc[im][jn], af[im][0], af[im][1], af[im][2], af[im][3],
                             bf[jn][0], bf[jn][1]);
        }

        // --- attn = mask ? exp(S/8)*inv : 0 -> stage (fp32) ---
#pragma unroll
        for (int im = 0; im < 4; im++) {
            const int rAl = wm * 64 + im * 16 + g;
            const int rBl = rAl + 8;
            const float ivA = invS[rAl], ivB = invS[rBl];
#pragma unroll
            for (int jn = 0; jn < 2; jn++) {
                const int bp = wn * 16 + jn * 8 + 2 * t;
                const unsigned int wA = maskA[rAl * 2 + (bp >> 5)];
                const unsigned int wB = maskA[rBl * 2 + (bp >> 5)];
                const int bi = bp & 31;
                float e0 = ((wA >> bi) & 1u)       ? __expf(acc[im][jn][0] * 0.125f) * ivA : 0.f;
                float e1 = ((wA >> (bi + 1)) & 1u) ? __expf(acc[im][jn][1] * 0.125f) * ivA : 0.f;
                float e2 = ((wB >> bi) & 1u)       ? __expf(acc[im][jn][2] * 0.125f) * ivB : 0.f;
                float e3 = ((wB >> (bi + 1)) & 1u) ? __expf(acc[im][jn][3] * 0.125f) * ivB : 0.f;
                *(float2*)&stage[rAl * 68 + bp] = make_float2(e0, e1);
                *(float2*)&stage[rBl * 68 + bp] = make_float2(e2, e3);
            }
        }
        // prefetch V(kt+1) (in flight across AV phase)
        float4 rv[4];
        if (pf) {
#pragma unroll
            for (int j = 0; j < 4; j++)
                rv[j] = *(const float4*)(Vbase + (size_t)(k0 + 64 + lr + j * 16) * HH + lc4);
        }
        __syncthreads();    // stage visible; QK done with Ks

        // --- coalesced attn write from stage (hoisted: STGs drain under MMA) ---
        float* abase = attn + ((size_t)(bh * SS + q0)) * SS + k0;
#pragma unroll
        for (int j = 0; j < 8; j++) {
            int idx = tid + j * 256;
            int r = idx >> 4, c4 = (idx & 15) * 4;
            float4 v = *(float4*)&stage[r * 68 + c4];
            *(float4*)(abase + (size_t)r * SS + c4) = v;
        }

        // --- AV MMA: O += P(stage, ldsm) * V(Vs row-major, direct LDS b-frags) ---
#pragma unroll
        for (int ks = 0; ks < 8; ks++) {
            const int kk = ks * 8;
            uint32_t af[4][4];
            float bf0[2], bf1[2];
#pragma unroll
            for (int im = 0; im < 4; im++)
                ldsm_x4(af[im], StU + (uint32_t)(rowQ[im] + kk) * 4);
#pragma unroll
            for (int jd = 0; jd < 2; jd++) {
                const int nc = wn * 16 + jd * 8 + g;
                bf0[jd] = Vs[(kk + t) * 68 + nc];
                bf1[jd] = Vs[(kk + t + 4) * 68 + nc];
            }
#pragma unroll
            for (int im = 0; im < 4; im++)
#pragma unroll
                for (int jd = 0; jd < 2; jd++)
                    MMA_TF32(accO[im][jd], af[im][0], af[im][1], af[im][2], af[im][3],
                             __float_as_uint(bf0[jd]), __float_as_uint(bf1[jd]));
        }
        __syncthreads();    // Ks/Vs/maskA free
        if (pf) {
#pragma unroll
            for (int j = 0; j < 4; j++) {
                int r = lr + j * 16;
                *(float4*)&Ks[r * 68 + lc4] = rk[j];
                *(float4*)&Vs[r * 68 + lc4] = rv[j];
            }
            maskA[tid] = rm;
        }
        __syncthreads();
    }

    // --- O epilogue ---
#pragma unroll
    for (int im = 0; im < 4; im++) {
        const int rowAo = q0 + wm * 64 + im * 16 + g;
        const int rowBo = rowAo + 8;
#pragma unroll
        for (int jd = 0; jd < 2; jd++) {
            const int col = h * HDD + wn * 16 + jd * 8 + 2 * t;
            *(float2*)(Ob + (size_t)(b * SS + rowAo) * HH + col) =
                make_float2(accO[im][jd][0], accO[im][jd][1]);
            *(float2*)(Ob + (size_t)(b * SS + rowBo) * HH + col) =
                make_float2(accO[im][jd][2], accO[im][jd][3]);
        }
    }
}

// ============================================================
// LayerNorm (vectorized)
// ============================================================
__global__ void __launch_bounds__(256)
ln_kernel(const float* __restrict__ X,
          const float* __restrict__ w,
          const float* __restrict__ bias,
          float* __restrict__ Y) {
    __shared__ float red[8];
    __shared__ float bc;
    const int row = blockIdx.x;
    const int tid = threadIdx.x, lane = tid & 31, warp = tid >> 5;

    float4 v = *(const float4*)(X + (size_t)row * HH + tid * 4);

    float s = v.x + v.y + v.z + v.w;
#pragma unroll
    for (int o = 16; o; o >>= 1) s += __shfl_xor_sync(0xffffffffu, s, o);
    if (lane == 0) red[warp] = s;
    __syncthreads();
    if (tid == 0) {
        float tt = 0.f;
        for (int i = 0; i < 8; i++) tt += red[i];
        bc = tt / HH;
    }
    __syncthreads();
    const float mu = bc;

    float d0 = v.x - mu, d1 = v.y - mu, d2 = v.z - mu, d3 = v.w - mu;
    float vv = d0 * d0 + d1 * d1 + d2 * d2 + d3 * d3;
#pragma unroll
    for (int o = 16; o; o >>= 1) vv += __shfl_xor_sync(0xffffffffu, vv, o);
    __syncthreads();
    if (lane == 0) red[warp] = vv;
    __syncthreads();
    if (tid == 0) {
        float tt = 0.f;
        for (int i = 0; i < 8; i++) tt += red[i];
        bc = rsqrtf(tt / HH + 1e-6f);
    }
    __syncthreads();
    const float inv = bc;

    float4 w4 = *(const float4*)(w + tid * 4);
    float4 b4 = *(const float4*)(bias + tid * 4);
    float4 out;
    out.x = d0 * inv * w4.x + b4.x;
    out.y = d1 * inv * w4.y + b4.y;
    out.z = d2 * inv * w4.z + b4.z;
    out.w = d3 * inv * w4.w + b4.w;
    *(float4*)(Y + (size_t)row * HH + tid * 4) = out;
}

// ============================================================
extern "C" void kernel_launch(void* const* d_in, const int* in_sizes, int n_in,
                              void* d_out, int out_size) {
    const float* enc  = (const float*)d_in[0];
    const float* mask = (const float*)d_in[1];
    const float* WQ   = (const float*)d_in[2];
    const float* WK   = (const float*)d_in[3];
    const float* WV   = (const float*)d_in[4];
    const float* WO   = (const float*)d_in[5];
    const float* lnw  = (const float*)d_in[6];
    const float* lnb  = (const float*)d_in[7];

    float* y    = (float*)d_out;              // (B,S,H)
    float* attn = y + (size_t)Y_SIZE;         // (B,NH,S,S)

    float *Qp, *Kp, *Vp, *Op, *Xp;
    unsigned int* Mp;
    cudaGetSymbolAddress((void**)&Qp, g_Q);
    cudaGetSymbolAddress((void**)&Kp, g_K);
    cudaGetSymbolAddress((void**)&Vp, g_V);
    cudaGetSymbolAddress((void**)&Op, g_AO);
    cudaGetSymbolAddress((void**)&Xp, g_X);
    cudaGetSymbolAddress((void**)&Mp, g_MB);

    qkv_gemm_kernel<<<dim3(HH / 128, MM / 128, 4), 256>>>(enc, WQ, WK, WV, mask,
                                                          Qp, Kp, Vp, Mp);

    const int fa_smem = 26752 * (int)sizeof(float);    // 107008
    cudaFuncSetAttribute(fused_attn_kernel,
                         cudaFuncAttributeMaxDynamicSharedMemorySize, fa_smem);
    fused_attn_kernel<<<dim3(SS / 128, BB * NHH), 256, fa_smem>>>(Qp, Kp, Vp, Mp, attn, Op);

    gemm_res_kernel<<<dim3(HH / 128, MM / 128), 256>>>(Op, WO, Xp, enc);

    ln_kernel<<<MM, 256>>>(Xp, lnw, lnb, y);
}

// round 16
// speedup vs baseline: 1.5280x; 1.5280x over previous
#include <cuda_runtime.h>
#include <math.h>
#include <stdint.h>

#define BB 2
#define SS 2048
#define HH 1024
#define NHH 16
#define HDD 64
#define MM (BB*SS)          // 4096
#define Y_SIZE (BB*SS*HH)   // 4194304

// ---- scratch (no allocation allowed; device globals) ----
__device__ float g_Q[MM*HH];
__device__ float g_K[MM*HH];
__device__ float g_V[MM*HH];
__device__ float g_AO[MM*HH];
__device__ float g_X[MM*HH];
__device__ unsigned int g_MB[BB*SS*SS/32];  // mask bits

__device__ __forceinline__ uint32_t f2tf32(float v) {
    uint32_t r;
    asm("cvt.rna.tf32.f32 %0, %1;" : "=r"(r) : "f"(v));
    return r;
}

#define MMA_TF32(acc, a0,a1,a2,a3, b0,b1) \
    asm volatile("mma.sync.aligned.m16n8k8.row.col.f32.tf32.tf32.f32 " \
        "{%0,%1,%2,%3}, {%4,%5,%6,%7}, {%8,%9}, {%0,%1,%2,%3};" \
        : "+f"((acc)[0]), "+f"((acc)[1]), "+f"((acc)[2]), "+f"((acc)[3]) \
        : "r"(a0), "r"(a1), "r"(a2), "r"(a3), "r"(b0), "r"(b1))

__device__ __forceinline__ void ldsm_x4(uint32_t* r, uint32_t addr) {
    asm volatile("ldmatrix.sync.aligned.m8n8.x4.shared.b16 {%0,%1,%2,%3}, [%4];"
        : "=r"(r[0]), "=r"(r[1]), "=r"(r[2]), "=r"(r[3]) : "r"(addr));
}
__device__ __forceinline__ void ldsm_x2(uint32_t* r, uint32_t addr) {
    asm volatile("ldmatrix.sync.aligned.m8n8.x2.shared.b16 {%0,%1}, [%2];"
        : "=r"(r[0]), "=r"(r[1]) : "r"(addr));
}
#define LDSM_SELS() \
    const int rsel = (lane & 7) + ((lane >> 3) & 1) * 8; \
    const int cA = (lane >> 4) * 4; \
    const int rB = lane & 7; \
    const int cB = ((lane >> 3) & 1) * 4;

// ============================================================
// GEMM body (tf32 warp-MMA, 128x128 tile, RNA rounding at smem store).
// ============================================================
#define GEMM_BODY(A_, W_, EPILOGUE)                                            \
    __shared__ float As[2][128 * 20];                                          \
    __shared__ float Ws[2][128 * 20];                                          \
    const int tid = threadIdx.x;                                               \
    const int wid = tid >> 5, lane = tid & 31;                                 \
    const int wm = wid >> 2, wn = wid & 3;                                     \
    const int bm = blockIdx.y * 128, bn = blockIdx.x * 128;                    \
    LDSM_SELS();                                                               \
    const uint32_t AsU = (uint32_t)__cvta_generic_to_shared(&As[0][0]);        \
    const uint32_t WsU = (uint32_t)__cvta_generic_to_shared(&Ws[0][0]);        \
    int rowA[4], rowB[4];                                                      \
    for (int im = 0; im < 4; im++) rowA[im] = (wm*64 + im*16 + rsel)*20 + cA;  \
    for (int jn = 0; jn < 4; jn++) rowB[jn] = (wn*32 + jn*8 + rB)*20 + cB;     \
    const int p0 = tid, p1 = tid + 256;                                        \
    const int r0 = p0 >> 2, q0 = (p0 & 3) * 4;                                 \
    const int r1 = p1 >> 2, q1 = (p1 & 3) * 4;                                 \
    const float* Arow0 = A_ + (size_t)(bm + r0) * 1024 + q0;                   \
    const float* Arow1 = A_ + (size_t)(bm + r1) * 1024 + q1;                   \
    const float* Wrow0 = W_ + (size_t)(bn + r0) * 1024 + q0;                   \
    const float* Wrow1 = W_ + (size_t)(bn + r1) * 1024 + q1;                   \
    const int s0 = r0 * 20 + q0, s1 = r1 * 20 + q1;                            \
    float acc[4][4][4];                                                        \
    for (int i = 0; i < 4; i++)                                                \
        for (int j = 0; j < 4; j++)                                            \
            for (int q = 0; q < 4; q++) acc[i][j][q] = 0.f;                    \
    {                                                                          \
        float4 va0 = *(const float4*)(Arow0);                                  \
        float4 va1 = *(const float4*)(Arow1);                                  \
        float4 vw0 = *(const float4*)(Wrow0);                                  \
        float4 vw1 = *(const float4*)(Wrow1);                                  \
        uint32_t* a0 = (uint32_t*)&As[0][s0];                                  \
        a0[0]=f2tf32(va0.x); a0[1]=f2tf32(va0.y); a0[2]=f2tf32(va0.z); a0[3]=f2tf32(va0.w); \
        uint32_t* a1 = (uint32_t*)&As[0][s1];                                  \
        a1[0]=f2tf32(va1.x); a1[1]=f2tf32(va1.y); a1[2]=f2tf32(va1.z); a1[3]=f2tf32(va1.w); \
        uint32_t* w0 = (uint32_t*)&Ws[0][s0];                                  \
        w0[0]=f2tf32(vw0.x); w0[1]=f2tf32(vw0.y); w0[2]=f2tf32(vw0.z); w0[3]=f2tf32(vw0.w); \
        uint32_t* w1 = (uint32_t*)&Ws[0][s1];                                  \
        w1[0]=f2tf32(vw1.x); w1[1]=f2tf32(vw1.y); w1[2]=f2tf32(vw1.z); w1[3]=f2tf32(vw1.w); \
    }                                                                          \
    __syncthreads();                                                           \
    for (int c = 0; c < 64; c++) {                                             \
        const int buf = c & 1;                                                 \
        const uint32_t aBuf = AsU + (uint32_t)buf * (128 * 20 * 4);            \
        const uint32_t wBuf = WsU + (uint32_t)buf * (128 * 20 * 4);            \
        float4 ra0, ra1, rw0, rw1;                                             \
        if (c < 63) {                                                          \
            const int k0 = (c + 1) * 16;                                       \
            ra0 = *(const float4*)(Arow0 + k0);                                \
            ra1 = *(const float4*)(Arow1 + k0);                                \
            rw0 = *(const float4*)(Wrow0 + k0);                                \
            rw1 = *(const float4*)(Wrow1 + k0);                                \
        }                                                                      \
        for (int ks = 0; ks < 2; ks++) {                                       \
            const int kk = ks * 8;                                             \
            uint32_t af[4][4], bf[4][2];                                       \
            for (int im = 0; im < 4; im++)                                     \
                ldsm_x4(af[im], aBuf + (uint32_t)(rowA[im] + kk) * 4);         \
            for (int jn = 0; jn < 4; jn++)                                     \
                ldsm_x2(bf[jn], wBuf + (uint32_t)(rowB[jn] + kk) * 4);         \
            for (int im = 0; im < 4; im++)                                     \
                for (int jn = 0; jn < 4; jn++)                                 \
                    MMA_TF32(acc[im][jn], af[im][0], af[im][1], af[im][2], af[im][3], \
                             bf[jn][0], bf[jn][1]);                            \
        }                                                                      \
        if (c < 63) {                                                          \
            const int nxt = buf ^ 1;                                           \
            uint32_t* a0 = (uint32_t*)&As[nxt][s0];                            \
            a0[0]=f2tf32(ra0.x); a0[1]=f2tf32(ra0.y); a0[2]=f2tf32(ra0.z); a0[3]=f2tf32(ra0.w); \
            uint32_t* a1 = (uint32_t*)&As[nxt][s1];                            \
            a1[0]=f2tf32(ra1.x); a1[1]=f2tf32(ra1.y); a1[2]=f2tf32(ra1.z); a1[3]=f2tf32(ra1.w); \
            uint32_t* w0 = (uint32_t*)&Ws[nxt][s0];                            \
            w0[0]=f2tf32(rw0.x); w0[1]=f2tf32(rw0.y); w0[2]=f2tf32(rw0.z); w0[3]=f2tf32(rw0.w); \
            uint32_t* w1 = (uint32_t*)&Ws[nxt][s1];                            \
            w1[0]=f2tf32(rw1.x); w1[1]=f2tf32(rw1.y); w1[2]=f2tf32(rw1.z); w1[3]=f2tf32(rw1.w); \
        }                                                                      \
        __syncthreads();                                                       \
    }                                                                          \
    const int g = lane >> 2, t = lane & 3;                                     \
    EPILOGUE

// QKV + maskbits fused launch: z in {0,1,2} -> GEMM (pre-rounded tf32 out),
// z==3 -> mask float -> bit conversion (overlaps bandwidth with GEMM latency).
__global__ void __launch_bounds__(256, 2)
qkv_gemm_kernel(const float* __restrict__ enc,
                const float* __restrict__ WQ, const float* __restrict__ WK,
                const float* __restrict__ WV, const float* __restrict__ mask,
                float* __restrict__ Qo, float* __restrict__ Ko, float* __restrict__ Vo,
                unsigned int* __restrict__ mb) {
    const int z = blockIdx.z;
    if (z == 3) {
        const int p = blockIdx.y * 8 + blockIdx.x;        // 0..255
        size_t base = (size_t)p * 32768 + threadIdx.x;
#pragma unroll 4
        for (int j = 0; j < 128; j++) {
            size_t i = base + (size_t)j * 256;
            float m = mask[i];
            unsigned int bal = __ballot_sync(0xffffffffu, m != 0.f);
            if ((threadIdx.x & 31) == 0) mb[i >> 5] = bal;
        }
        return;
    }
    const float* Wsel = (z == 0) ? WQ : (z == 1) ? WK : WV;
    float* Csel = (z == 0) ? Qo : (z == 1) ? Ko : Vo;
    GEMM_BODY(enc, Wsel,
        {
            for (int im = 0; im < 4; im++) {
                const int rowAo = bm + wm * 64 + im * 16 + g;
                const int rowBo = rowAo + 8;
                for (int jn = 0; jn < 4; jn++) {
                    const int col = bn + wn * 32 + jn * 8 + 2 * t;
                    float2 vA = make_float2(__uint_as_float(f2tf32(acc[im][jn][0])),
                                            __uint_as_float(f2tf32(acc[im][jn][1])));
                    float2 vB = make_float2(__uint_as_float(f2tf32(acc[im][jn][2])),
                                            __uint_as_float(f2tf32(acc[im][jn][3])));
                    *(float2*)(Csel + (size_t)rowAo * 1024 + col) = vA;
                    *(float2*)(Csel + (size_t)rowBo * 1024 + col) = vB;
                }
            }
        })
}

// WO: residual-add epilogue, full fp32 output.
__global__ void __launch_bounds__(256, 2)
gemm_res_kernel(const float* __restrict__ A, const float* __restrict__ W,
                float* __restrict__ C, const float* __restrict__ res) {
    GEMM_BODY(A, W,
        {
            for (int im = 0; im < 4; im++) {
                const int rowAo = bm + wm * 64 + im * 16 + g;
                const int rowBo = rowAo + 8;
                for (int jn = 0; jn < 4; jn++) {
                    const int col = bn + wn * 32 + jn * 8 + 2 * t;
                    float2 rA = *(const float2*)(res + (size_t)rowAo * 1024 + col);
                    float2 rB2 = *(const float2*)(res + (size_t)rowBo * 1024 + col);
                    *(float2*)(C + (size_t)rowAo * 1024 + col) =
                        make_float2(acc[im][jn][0] + rA.x, acc[im][jn][1] + rA.y);
                    *(float2*)(C + (size_t)rowBo * 1024 + col) =
                        make_float2(acc[im][jn][2] + rB2.x, acc[im][jn][3] + rB2.y);
                }
            }
        })
}

// ============================================================
// Fused attention (R12/R14 layout): phase 1 row sums (64-col K tiles,
// register prefetch, 2 syncs/tile), phase 2 S recompute + single attn
// write + AV MMA. Q/K/V pre-rounded tf32 -> raw float4 loads. V row-major;
// AV B-frags via direct LDS.
// smem floats: Qs[8704]@0, Ks[4352]@8704, Vs[4352]@13056, stage[8704]@17408
// (phase-1 sumbuf overlays stage), maskS(256u)@26112, invS[128]@26368.
// ============================================================
__global__ void __launch_bounds__(256, 2)
fused_attn_kernel(const float* __restrict__ Qb, const float* __restrict__ Kb,
                  const float* __restrict__ Vb, const unsigned int* __restrict__ mb,
                  float* __restrict__ attn, float* __restrict__ Ob) {
    extern __shared__ float sm[];
    float* Qs = sm;
    float* Ks = sm + 8704;
    float* Vs = sm + 13056;
    float* stage = sm + 17408;
    float* sumbuf = sm + 17408;                         // overlays stage (phase 1)
    unsigned int* maskS = (unsigned int*)(sm + 26112);
    float* invS = sm + 26368;

    const int tid = threadIdx.x;
    const int wid = tid >> 5, lane = tid & 31;
    const int wm = wid >> 2, wn = wid & 3;
    const int bh = blockIdx.y, b = bh >> 4, h = bh & 15;
    const int q0 = blockIdx.x * 128;
    LDSM_SELS();
    const int g = lane >> 2, t = lane & 3;

    const uint32_t QsU = (uint32_t)__cvta_generic_to_shared(Qs);
    const uint32_t KsU = (uint32_t)__cvta_generic_to_shared(Ks);
    const uint32_t StU = (uint32_t)__cvta_generic_to_shared(stage);

    int rowQ[4], rowK[2];
#pragma unroll
    for (int im = 0; im < 4; im++) rowQ[im] = (wm * 64 + im * 16 + rsel) * 68 + cA;
#pragma unroll
    for (int jn = 0; jn < 2; jn++) rowK[jn] = (wn * 16 + jn * 8 + rB) * 68 + cB;

    const float* Qbase = Qb + ((size_t)(b * SS + q0)) * HH + h * HDD;
    const float* Kbase = Kb + ((size_t)b * SS) * HH + h * HDD;
    const float* Vbase = Vb + ((size_t)b * SS) * HH + h * HDD;
    const int lr = tid >> 4, lc4 = (tid & 15) * 4;
    const int mr = tid >> 1, mw = tid & 1;

    // Q loaded once for both phases
#pragma unroll
    for (int j = 0; j < 8; j++) {
        int idx = tid + j * 256;
        int r = idx >> 4, c4 = (idx & 15) * 4;
        *(float4*)&Qs[r * 68 + c4] = *(const float4*)(Qbase + (size_t)r * HH + c4);
    }
    // phase-1 tile 0: K + mask
#pragma unroll
    for (int j = 0; j < 4; j++) {
        int r = lr + j * 16;
        *(float4*)&Ks[r * 68 + lc4] = *(const float4*)(Kbase + (size_t)r * HH + lc4);
    }
    maskS[tid] = mb[(size_t)(b * SS + q0 + mr) * 64 + mw];
    __syncthreads();

    // ================= PHASE 1: row sums =================
    float rsA[4], rsB[4];
#pragma unroll
    for (int im = 0; im < 4; im++) { rsA[im] = 0.f; rsB[im] = 0.f; }

    for (int kt = 0; kt < 32; kt++) {
        const bool pf = (kt < 31);
        float4 rk[4];
        unsigned int rm = 0;
        if (pf) {
            const int n1 = (kt + 1) * 64;
#pragma unroll
            for (int j = 0; j < 4; j++)
                rk[j] = *(const float4*)(Kbase + (size_t)(n1 + lr + j * 16) * HH + lc4);
            rm = mb[(size_t)(b * SS + q0 + mr) * 64 + (n1 >> 5) + mw];
        }

        float acc[4][2][4];
#pragma unroll
        for (int i = 0; i < 4; i++)
#pragma unroll
            for (int j = 0; j < 2; j++)
#pragma unroll
                for (int q = 0; q < 4; q++) acc[i][j][q] = 0.f;
#pragma unroll
        for (int ks = 0; ks < 8; ks++) {
            const int kk = ks * 8;
            uint32_t af[4][4], bf[2][2];
#pragma unroll
            for (int im = 0; im < 4; im++)
                ldsm_x4(af[im], QsU + (uint32_t)(rowQ[im] + kk) * 4);
#pragma unroll
            for (int jn = 0; jn < 2; jn++)
                ldsm_x2(bf[jn], KsU + (uint32_t)(rowK[jn] + kk) * 4);
#pragma unroll
            for (int im = 0; im < 4; im++)
#pragma unroll
                for (int jn = 0; jn < 2; jn++)
                    MMA_TF32(acc[im][jn], af[im][0], af[im][1], af[im][2], af[im][3],
                             bf[jn][0], bf[jn][1]);
        }

#pragma unroll
        for (int im = 0; im < 4; im++) {
            const int rAl = wm * 64 + im * 16 + g;
            const int rBl = rAl + 8;
#pragma unroll
            for (int jn = 0; jn < 2; jn++) {
                const int bp = wn * 16 + jn * 8 + 2 * t;
                const unsigned int wA = maskS[rAl * 2 + (bp >> 5)];
                const unsigned int wB = maskS[rBl * 2 + (bp >> 5)];
                const int bi = bp & 31;
                if ((wA >> bi) & 1u)       rsA[im] += __expf(acc[im][jn][0] * 0.125f);
                if ((wA >> (bi + 1)) & 1u) rsA[im] += __expf(acc[im][jn][1] * 0.125f);
                if ((wB >> bi) & 1u)       rsB[im] += __expf(acc[im][jn][2] * 0.125f);
                if ((wB >> (bi + 1)) & 1u) rsB[im] += __expf(acc[im][jn][3] * 0.125f);
            }
        }
        __syncthreads();
        if (pf) {
#pragma unroll
            for (int j = 0; j < 4; j++)
                *(float4*)&Ks[(lr + j * 16) * 68 + lc4] = rk[j];
            maskS[tid] = rm;
        }
        __syncthreads();
    }

#pragma unroll
    for (int im = 0; im < 4; im++) {
        float a = rsA[im], bb = rsB[im];
        a += __shfl_xor_sync(0xffffffffu, a, 1);
        a += __shfl_xor_sync(0xffffffffu, a, 2);
        bb += __shfl_xor_sync(0xffffffffu, bb, 1);
        bb += __shfl_xor_sync(0xffffffffu, bb, 2);
        if (t == 0) {
            sumbuf[(wm * 64 + im * 16 + g) * 4 + wn] = a;
            sumbuf[(wm * 64 + im * 16 + g + 8) * 4 + wn] = bb;
        }
    }
    __syncthreads();
    if (tid < 128) {
        float s = sumbuf[tid * 4] + sumbuf[tid * 4 + 1] +
                  sumbuf[tid * 4 + 2] + sumbuf[tid * 4 + 3];
        invS[tid] = (s > 0.f) ? 1.f / s : 0.f;
    }
    // phase-2 tile 0: K, V (row-major), mask
    __syncthreads();
#pragma unroll
    for (int j = 0; j < 4; j++) {
        int r = lr + j * 16;
        *(float4*)&Ks[r * 68 + lc4] = *(const float4*)(Kbase + (size_t)r * HH + lc4);
        *(float4*)&Vs[r * 68 + lc4] = *(const float4*)(Vbase + (size_t)r * HH + lc4);
    }
    maskS[tid] = mb[(size_t)(b * SS + q0 + mr) * 64 + mw];
    __syncthreads();

    // ================= PHASE 2: attn write + AV =================
    float accO[4][2][4];
#pragma unroll
    for (int i = 0; i < 4; i++)
#pragma unroll
        for (int j = 0; j < 2; j++)
#pragma unroll
            for (int q = 0; q < 4; q++) accO[i][j][q] = 0.f;

    for (int kt = 0; kt < 32; kt++) {
        const int k0 = kt * 64;
        const bool pf = (kt < 31);
        float4 rk[4];
        unsigned int rm = 0;
        if (pf) {
#pragma unroll
            for (int j = 0; j < 4; j++)
                rk[j] = *(const float4*)(Kbase + (size_t)(k0 + 64 + lr + j * 16) * HH + lc4);
            rm = mb[(size_t)(b * SS + q0 + mr) * 64 + ((k0 + 64) >> 5) + mw];
        }

        // --- S = Q K^T ---
        float acc[4][2][4];
#pragma unroll
        for (int i = 0; i < 4; i++)
#pragma unroll
            for (int j = 0; j < 2; j++)
#pragma unroll
                for (int q = 0; q < 4; q++) acc[i][j][q] = 0.f;
#pragma unroll
        for (int ks = 0; ks < 8; ks++) {
            const int kk = ks * 8;
            uint32_t af[4][4], bf[2][2];
#pragma unroll
            for (int im = 0; im < 4; im++)
                ldsm_x4(af[im], QsU + (uint32_t)(rowQ[im] + kk) * 4);
#pragma unroll
            for (int jn = 0; jn < 2; jn++)
                ldsm_x2(bf[jn], KsU + (uint32_t)(rowK[jn] + kk) * 4);
#pragma unroll
            for (int im = 0; im < 4; im++)
#pragma unroll
                for (int jn = 0; jn < 2; jn++)
                    MMA_TF32(acc[im][jn], af[im][0], af[im][1], af[im][2], af[im][3],
                             bf[jn][0], bf[jn][1]);
        }

        // --- attn = mask ? exp(S/8)*inv : 0 -> stage (fp32) ---
#pragma unroll
        for (int im = 0; im < 4; im++) {
            const int rAl = wm * 64 + im * 16 + g;
            const int rBl = rAl + 8;
            const float ivA = invS[rAl], ivB = invS[rBl];
#pragma unroll
            for (int jn = 0; jn < 2; jn++) {
                const int bp = wn * 16 + jn * 8 + 2 * t;
                const unsigned int wA = maskS[rAl * 2 + (bp >> 5)];
                const unsigned int wB = maskS[rBl * 2 + (bp >> 5)];
                const int bi = bp & 31;
                float e0 = ((wA >> bi) & 1u)       ? __expf(acc[im][jn][0] * 0.125f) * ivA : 0.f;
                float e1 = ((wA >> (bi + 1)) & 1u) ? __expf(acc[im][jn][1] * 0.125f) * ivA : 0.f;
                float e2 = ((wB >> bi) & 1u)       ? __expf(acc[im][jn][2] * 0.125f) * ivB : 0.f;
                float e3 = ((wB >> (bi + 1)) & 1u) ? __expf(acc[im][jn][3] * 0.125f) * ivB : 0.f;
                *(float2*)&stage[rAl * 68 + bp] = make_float2(e0, e1);
                *(float2*)&stage[rBl * 68 + bp] = make_float2(e2, e3);
            }
        }
        // prefetch V(kt+1) (in flight across AV phase)
        float4 rv[4];
        if (pf) {
#pragma unroll
            for (int j = 0; j < 4; j++)
                rv[j] = *(const float4*)(Vbase + (size_t)(k0 + 64 + lr + j * 16) * HH + lc4);
        }
        __syncthreads();    // stage visible; QK done with Ks

        // --- AV MMA: O += P(stage, ldsm) * V(Vs row-major, direct LDS b-frags) ---
#pragma unroll
        for (int ks = 0; ks < 8; ks++) {
            const int kk = ks * 8;
            uint32_t af[4][4];
            float bf0[2], bf1[2];
#pragma unroll
            for (int im = 0; im < 4; im++)
                ldsm_x4(af[im], StU + (uint32_t)(rowQ[im] + kk) * 4);
#pragma unroll
            for (int jd = 0; jd < 2; jd++) {
                const int nc = wn * 16 + jd * 8 + g;
                bf0[jd] = Vs[(kk + t) * 68 + nc];
                bf1[jd] = Vs[(kk + t + 4) * 68 + nc];
            }
#pragma unroll
            for (int im = 0; im < 4; im++)
#pragma unroll
                for (int jd = 0; jd < 2; jd++)
                    MMA_TF32(accO[im][jd], af[im][0], af[im][1], af[im][2], af[im][3],
                             __float_as_uint(bf0[jd]), __float_as_uint(bf1[jd]));
        }

        // --- coalesced attn write from stage ---
        float* abase = attn + ((size_t)(bh * SS + q0)) * SS + k0;
#pragma unroll
        for (int j = 0; j < 8; j++) {
            int idx = tid + j * 256;
            int r = idx >> 4, c4 = (idx & 15) * 4;
            float4 v = *(float4*)&stage[r * 68 + c4];
            *(float4*)(abase + (size_t)r * SS + c4) = v;
        }
        __syncthreads();    // Ks/Vs/maskS free
        if (pf) {
#pragma unroll
            for (int j = 0; j < 4; j++) {
                int r = lr + j * 16;
                *(float4*)&Ks[r * 68 + lc4] = rk[j];
                *(float4*)&Vs[r * 68 + lc4] = rv[j];
            }
            maskS[tid] = rm;
        }
        __syncthreads();
    }

    // --- O epilogue ---
#pragma unroll
    for (int im = 0; im < 4; im++) {
        const int rowAo = q0 + wm * 64 + im * 16 + g;
        const int rowBo = rowAo + 8;
#pragma unroll
        for (int jd = 0; jd < 2; jd++) {
            const int col = h * HDD + wn * 16 + jd * 8 + 2 * t;
            *(float2*)(Ob + (size_t)(b * SS + rowAo) * HH + col) =
                make_float2(accO[im][jd][0], accO[im][jd][1]);
            *(float2*)(Ob + (size_t)(b * SS + rowBo) * HH + col) =
                make_float2(accO[im][jd][2], accO[im][jd][3]);
        }
    }
}

// ============================================================
// LayerNorm (vectorized: one float4 per thread, x read once)
// ============================================================
__global__ void __launch_bounds__(256)
ln_kernel(const float* __restrict__ X,
          const float* __restrict__ w,
          const float* __restrict__ bias,
          float* __restrict__ Y) {
    __shared__ float red[8];
    __shared__ float bc;
    const int row = blockIdx.x;
    const int tid = threadIdx.x, lane = tid & 31, warp = tid >> 5;

    float4 v = *(const float4*)(X + (size_t)row * HH + tid * 4);

    float s = v.x + v.y + v.z + v.w;
#pragma unroll
    for (int o = 16; o; o >>= 1) s += __shfl_xor_sync(0xffffffffu, s, o);
    if (lane == 0) red[warp] = s;
    __syncthreads();
    if (tid == 0) {
        float tt = 0.f;
        for (int i = 0; i < 8; i++) tt += red[i];
        bc = tt / HH;
    }
    __syncthreads();
    const float mu = bc;

    float d0 = v.x - mu, d1 = v.y - mu, d2 = v.z - mu, d3 = v.w - mu;
    float vv = d0 * d0 + d1 * d1 + d2 * d2 + d3 * d3;
#pragma unroll
    for (int o = 16; o; o >>= 1) vv += __shfl_xor_sync(0xffffffffu, vv, o);
    __syncthreads();
    if (lane == 0) red[warp] = vv;
    __syncthreads();
    if (tid == 0) {
        float tt = 0.f;
        for (int i = 0; i < 8; i++) tt += red[i];
        bc = rsqrtf(tt / HH + 1e-6f);
    }
    __syncthreads();
    const float inv = bc;

    float4 w4 = *(const float4*)(w + tid * 4);
    float4 b4 = *(const float4*)(bias + tid * 4);
    float4 out;
    out.x = d0 * inv * w4.x + b4.x;
    out.y = d1 * inv * w4.y + b4.y;
    out.z = d2 * inv * w4.z + b4.z;
    out.w = d3 * inv * w4.w + b4.w;
    *(float4*)(Y + (size_t)row * HH + tid * 4) = out;
}

// ============================================================
extern "C" void kernel_launch(void* const* d_in, const int* in_sizes, int n_in,
                              void* d_out, int out_size) {
    const float* enc  = (const float*)d_in[0];
    const float* mask = (const float*)d_in[1];
    const float* WQ   = (const float*)d_in[2];
    const float* WK   = (const float*)d_in[3];
    const float* WV   = (const float*)d_in[4];
    const float* WO   = (const float*)d_in[5];
    const float* lnw  = (const float*)d_in[6];
    const float* lnb  = (const float*)d_in[7];

    float* y    = (float*)d_out;              // (B,S,H)
    float* attn = y + (size_t)Y_SIZE;         // (B,NH,S,S)

    float *Qp, *Kp, *Vp, *Op, *Xp;
    unsigned int* Mp;
    cudaGetSymbolAddress((void**)&Qp, g_Q);
    cudaGetSymbolAddress((void**)&Kp, g_K);
    cudaGetSymbolAddress((void**)&Vp, g_V);
    cudaGetSymbolAddress((void**)&Op, g_AO);
    cudaGetSymbolAddress((void**)&Xp, g_X);
    cudaGetSymbolAddress((void**)&Mp, g_MB);

    qkv_gemm_kernel<<<dim3(HH / 128, MM / 128, 4), 256>>>(enc, WQ, WK, WV, mask,
                                                          Qp, Kp, Vp, Mp);

    const int fa_smem = 26496 * (int)sizeof(float);    // 105984
    cudaFuncSetAttribute(fused_attn_kernel,
                         cudaFuncAttributeMaxDynamicSharedMemorySize, fa_smem);
    fused_attn_kernel<<<dim3(SS / 128, BB * NHH), 256, fa_smem>>>(Qp, Kp, Vp, Mp, attn, Op);

    gemm_res_kernel<<<dim3(HH / 128, MM / 128), 256>>>(Op, WO, Xp, enc);

    ln_kernel<<<MM, 256>>>(Xp, lnw, lnb, y);
}